// round 6
// baseline (speedup 1.0000x reference)
#include <cuda_runtime.h>
#include <cstdint>

// Problem constants
#define Bd 4
#define Cd 256
#define Hd 8
#define NPIX 16384

__device__ float g_Q[NPIX*Cd];
__device__ float g_K[NPIX*Cd];
__device__ float g_V[NPIX*Cd];
__device__ float g_att[NPIX*Cd];

typedef unsigned long long u64;

__device__ __forceinline__ u64 ffma2(u64 a, u64 b, u64 c) {
    u64 d;
    asm("fma.rn.f32x2 %0, %1, %2, %3;" : "=l"(d) : "l"(a), "l"(b), "l"(c));
    return d;
}
__device__ __forceinline__ u64 fadd2(u64 a, u64 b) {
    u64 d;
    asm("add.rn.f32x2 %0, %1, %2;" : "=l"(d) : "l"(a), "l"(b));
    return d;
}
__device__ __forceinline__ u64 pack2(float x, float y) {
    u64 d;
    asm("mov.b64 %0, {%1, %2};" : "=l"(d) : "r"(__float_as_uint(x)), "r"(__float_as_uint(y)));
    return d;
}
__device__ __forceinline__ float2 unpack2(u64 a) {
    unsigned lo, hi;
    asm("mov.b64 {%0, %1}, %2;" : "=r"(lo), "=r"(hi) : "l"(a));
    return make_float2(__uint_as_float(lo), __uint_as_float(hi));
}

// ---------------------------------------------------------------------------
// SGEMM via FFMA2: C[M x 256] = A[M x 256] @ B[256 x 256]
// BM=128, BN=128, BK=16, 256 threads, 8x8/thread as 8x4 f32x2 accumulators.
// A stored DUPLICATED in smem so the broadcast side loads directly as pairs.
// ---------------------------------------------------------------------------
#define GBM 128
#define GBN 128
#define GBK 16
#define ASTR 264   // floats per k-row of As_dup (256 dup + 8 pad: conflict-free)

__device__ __forceinline__ void sgemm2(const float* __restrict__ A,
                                       const float* __restrict__ B,
                                       float* __restrict__ C,
                                       const float* __restrict__ pos,
                                       bool addpos)
{
    __shared__ float As[2][GBK * ASTR];   // dup pairs: [k][2*row], [k][2*row+1]
    __shared__ float Bs[2][GBK][GBN];

    const int t   = threadIdx.x;
    const int m0  = blockIdx.y * GBM;
    const int n0  = blockIdx.x * GBN;
    const int tm0 = (t >> 4) << 3;    // row block (8 rows)
    const int tn0 = (t & 15) << 3;    // col block (8 cols = 4 pairs)

    const int ar0  = t >> 2;          // 0..63
    const int akc  = (t & 3) << 2;    // 0,4,8,12
    const int brow = t >> 5;          // 0..7
    const int bcol = (t & 31) << 2;   // 0..124

    float4 pa0, pa1, pb0, pb1;

    auto ldg = [&](int k0) {
        pa0 = *(const float4*)(A + (size_t)(m0 + ar0)      * 256 + k0 + akc);
        pa1 = *(const float4*)(A + (size_t)(m0 + 64 + ar0) * 256 + k0 + akc);
        pb0 = *(const float4*)(B + (size_t)(k0 + brow)     * 256 + n0 + bcol);
        pb1 = *(const float4*)(B + (size_t)(k0 + brow + 8) * 256 + n0 + bcol);
    };
    auto sts = [&](int buf) {
        float v0[4] = {pa0.x, pa0.y, pa0.z, pa0.w};
        float v1[4] = {pa1.x, pa1.y, pa1.z, pa1.w};
#pragma unroll
        for (int j = 0; j < 4; j++) {
            *(u64*)(&As[buf][(akc + j) * ASTR + 2 * ar0])         = pack2(v0[j], v0[j]);
            *(u64*)(&As[buf][(akc + j) * ASTR + 128 + 2 * ar0])   = pack2(v1[j], v1[j]);
        }
        *(float4*)(&Bs[buf][brow][bcol])     = pb0;
        *(float4*)(&Bs[buf][brow + 8][bcol]) = pb1;
    };

    u64 acc2[8][4];
#pragma unroll
    for (int i = 0; i < 8; i++)
#pragma unroll
        for (int j = 0; j < 4; j++) acc2[i][j] = 0ull;

    ldg(0); sts(0); __syncthreads();

    for (int kt = 0; kt < 16; kt++) {
        const int buf = kt & 1;
        const bool more = (kt < 15);
        if (more) ldg((kt + 1) << 4);
#pragma unroll
        for (int k = 0; k < GBK; k++) {
            u64 a2[8], b2[4];
            const ulonglong2* ap = (const ulonglong2*)(&As[buf][k * ASTR + 2 * tm0]);
            const ulonglong2* bp = (const ulonglong2*)(&Bs[buf][k][tn0]);
            ulonglong2 A01 = ap[0], A23 = ap[1], A45 = ap[2], A67 = ap[3];
            ulonglong2 B01 = bp[0], B23 = bp[1];
            a2[0]=A01.x; a2[1]=A01.y; a2[2]=A23.x; a2[3]=A23.y;
            a2[4]=A45.x; a2[5]=A45.y; a2[6]=A67.x; a2[7]=A67.y;
            b2[0]=B01.x; b2[1]=B01.y; b2[2]=B23.x; b2[3]=B23.y;
#pragma unroll
            for (int i = 0; i < 8; i++)
#pragma unroll
                for (int j = 0; j < 4; j++)
                    acc2[i][j] = ffma2(a2[i], b2[j], acc2[i][j]);
        }
        if (more) { sts(buf ^ 1); __syncthreads(); }
    }

#pragma unroll
    for (int i = 0; i < 8; i++) {
        const int m = m0 + tm0 + i;
        float2 c0 = unpack2(acc2[i][0]);
        float2 c1 = unpack2(acc2[i][1]);
        float2 c2 = unpack2(acc2[i][2]);
        float2 c3 = unpack2(acc2[i][3]);
        float4 v0 = make_float4(c0.x, c0.y, c1.x, c1.y);
        float4 v1 = make_float4(c2.x, c2.y, c3.x, c3.y);
        if (addpos) {
            int y  = (m >> 6) & 63;
            int x  = m & 63;
            int qy = y - min(max(y, 3), 60) + 3;
            int qx = x - min(max(x, 3), 60) + 3;
            const float* pe = pos + (size_t)(qy * 7 + qx) * 256 + n0 + tn0;
            const float4 p0 = *(const float4*)(pe);
            const float4 p1 = *(const float4*)(pe + 4);
            v0.x += p0.x; v0.y += p0.y; v0.z += p0.z; v0.w += p0.w;
            v1.x += p1.x; v1.y += p1.y; v1.z += p1.z; v1.w += p1.w;
        }
        *(float4*)(C + (size_t)m * 256 + n0 + tn0)     = v0;
        *(float4*)(C + (size_t)m * 256 + n0 + tn0 + 4) = v1;
    }
}

__global__ __launch_bounds__(256) void qkv_kernel(const float* __restrict__ X,
                                                  const float* __restrict__ Wq,
                                                  const float* __restrict__ Wk,
                                                  const float* __restrict__ Wv,
                                                  const float* __restrict__ pos)
{
    int mat = blockIdx.z;
    const float* W = (mat == 0) ? Wq : ((mat == 1) ? Wk : Wv);
    float* O       = (mat == 0) ? g_Q : ((mat == 1) ? g_K : g_V);
    sgemm2(X, W, O, pos, mat == 0);
}

__global__ __launch_bounds__(256) void out_kernel(const float* __restrict__ Wo,
                                                  float* __restrict__ out)
{
    sgemm2(g_att, Wo, out, nullptr, false);
}

// ---------------------------------------------------------------------------
// Attention: thread = (pixel, head). Block = 16x8 pixel tile, 1 head, 128 thr.
// All math in packed f32x2. P loads are warp-broadcast. No Q staging.
// ---------------------------------------------------------------------------
#define TW 16
#define TH 8
#define HW 22
#define NR (HW*14)   // 308

__global__ __launch_bounds__(128) void attn_kernel(const float* __restrict__ pos)
{
    extern __shared__ float4 sm4[];
    float4* Ks4 = sm4;                 // [8][NR]
    float4* Vs4 = sm4 + 8 * NR;        // [8][NR]
    float4* Ps4 = sm4 + 16 * NR;       // [8][49]

    const int bx = blockIdx.x;         // 0..31
    const int h  = blockIdx.y;
    const int b  = blockIdx.z;
    const int Ty = (bx >> 2) * TH;
    const int Tx = (bx & 3) * TW;
    const int t  = threadIdx.x;
    const int hb = h * 32;

    for (int i = t; i < NR * 8; i += 128) {
        int r  = i >> 3;
        int f4 = i & 7;
        int ry = r / HW;
        int rx = r - ry * HW;
        int gy = min(max(Ty - 3 + ry, 0), 63);
        int gx = min(max(Tx - 3 + rx, 0), 63);
        size_t off = ((size_t)(((b << 6) + gy) << 6) + gx) * 256 + hb + (f4 << 2);
        Ks4[f4 * NR + r] = *(const float4*)(g_K + off);
        Vs4[f4 * NR + r] = *(const float4*)(g_V + off);
    }
    for (int i = t; i < 49 * 8; i += 128) {
        int s  = i >> 3;
        int f4 = i & 7;
        Ps4[f4 * 49 + s] = *(const float4*)(pos + (size_t)s * 256 + hb + (f4 << 2));
    }
    __syncthreads();

    const int py = t >> 4, px = t & 15;
    const int gy = Ty + py, gx = Tx + px;
    const int pr0 = min(max(gy, 3), 60) - Ty;
    const int pc0 = min(max(gx, 3), 60) - Tx;

    const float scale = 0.17677669529663687f;  // 1/sqrt(32)
    const size_t gp = ((size_t)(((b << 6) + gy) << 6) + gx) * 256 + hb;

    u64 q2[16];
#pragma unroll
    for (int f4 = 0; f4 < 8; f4++) {
        const float4 v = *(const float4*)(g_Q + gp + (f4 << 2));
        q2[2 * f4]     = pack2(v.x * scale, v.y * scale);
        q2[2 * f4 + 1] = pack2(v.z * scale, v.w * scale);
    }

    u64 acc2[16];
#pragma unroll
    for (int i = 0; i < 16; i++) acc2[i] = 0ull;
    float l = 0.f;

#pragma unroll 1
    for (int dy = 0; dy < 7; dy++) {
        const int r0 = (pr0 + dy) * HW + pc0;
        const int s0 = dy * 7;
#pragma unroll
        for (int dx = 0; dx < 7; dx++) {
            const int r = r0 + dx;
            const int s = s0 + dx;
            u64 d0 = 0ull, d1 = 0ull, d2 = 0ull, d3 = 0ull;
#pragma unroll
            for (int f4 = 0; f4 < 8; f4++) {
                const ulonglong2 kk = *(const ulonglong2*)(Ks4 + f4 * NR + r);
                const ulonglong2 pp = *(const ulonglong2*)(Ps4 + f4 * 49 + s);
                if (f4 & 1) {
                    d2 = ffma2(q2[2 * f4],     fadd2(kk.x, pp.x), d2);
                    d3 = ffma2(q2[2 * f4 + 1], fadd2(kk.y, pp.y), d3);
                } else {
                    d0 = ffma2(q2[2 * f4],     fadd2(kk.x, pp.x), d0);
                    d1 = ffma2(q2[2 * f4 + 1], fadd2(kk.y, pp.y), d1);
                }
            }
            const float2 sv = unpack2(fadd2(fadd2(d0, d1), fadd2(d2, d3)));
            const float w = __expf(sv.x + sv.y);
            l += w;
            const u64 w2 = pack2(w, w);
#pragma unroll
            for (int f4 = 0; f4 < 8; f4++) {
                const ulonglong2 vv = *(const ulonglong2*)(Vs4 + f4 * NR + r);
                acc2[2 * f4]     = ffma2(w2, vv.x, acc2[2 * f4]);
                acc2[2 * f4 + 1] = ffma2(w2, vv.y, acc2[2 * f4 + 1]);
            }
        }
    }

    const float inv = __fdividef(1.f, l + 1e-8f);
#pragma unroll
    for (int f4 = 0; f4 < 8; f4++) {
        const float2 a = unpack2(acc2[2 * f4]);
        const float2 c = unpack2(acc2[2 * f4 + 1]);
        float4 o = make_float4(a.x * inv, a.y * inv, c.x * inv, c.y * inv);
        *(float4*)(g_att + gp + (f4 << 2)) = o;
    }
}

// ---------------------------------------------------------------------------
extern "C" void kernel_launch(void* const* d_in, const int* in_sizes, int n_in,
                              void* d_out, int out_size)
{
    const float* x   = (const float*)d_in[0];
    const float* Wq  = (const float*)d_in[1];
    const float* Wk  = (const float*)d_in[2];
    const float* Wv  = (const float*)d_in[3];
    const float* Wo  = (const float*)d_in[4];
    const float* pos = (const float*)d_in[5];

    // 1) QKV projections (+pos epilogue on Q)
    qkv_kernel<<<dim3(Cd / GBN, NPIX / GBM, 3), 256>>>(x, Wq, Wk, Wv, pos);

    // 2) Local attention
    const int smem = (16 * NR + 8 * 49) * (int)sizeof(float4); // 85120 B
    cudaFuncSetAttribute(attn_kernel, cudaFuncAttributeMaxDynamicSharedMemorySize, smem);
    attn_kernel<<<dim3(32, Hd, Bd), 128, smem>>>(pos);

    // 3) Output projection
    out_kernel<<<dim3(Cd / GBN, NPIX / GBM, 1), 256>>>(Wo, (float*)d_out);
}

// round 8
// speedup vs baseline: 1.2144x; 1.2144x over previous
#include <cuda_runtime.h>

// Problem constants
#define Bd 4
#define Cd 256
#define Hd 8
#define NPIX 16384

__device__ float g_Q[NPIX*Cd];
__device__ float g_K[NPIX*Cd];
__device__ float g_V[NPIX*Cd];
__device__ float g_att[NPIX*Cd];

// ---------------------------------------------------------------------------
// SGEMM (R1-proven): C[M x 256] = A[M x 256] @ B[256 x 256]
// BM=128, BN=64, BK=16, 256 threads, 8x4 per thread
// ---------------------------------------------------------------------------
#define GBM 128
#define GBN 64
#define GBK 16

__device__ __forceinline__ void sgemm_256(const float* __restrict__ A,
                                          const float* __restrict__ B,
                                          float* __restrict__ C,
                                          const float* __restrict__ pos,
                                          bool addpos)
{
    __shared__ float As[GBK][GBM + 1];
    __shared__ float Bs[GBK][GBN];
    const int t   = threadIdx.x;
    const int m0  = blockIdx.y * GBM;
    const int n0  = blockIdx.x * GBN;
    const int tm0 = (t >> 4) << 3;   // 0..120 step 8
    const int tn0 = (t & 15) << 2;   // 0..60  step 4

    float acc[8][4];
#pragma unroll
    for (int i = 0; i < 8; i++)
#pragma unroll
        for (int j = 0; j < 4; j++) acc[i][j] = 0.f;

    for (int k0 = 0; k0 < 256; k0 += GBK) {
        // Load A tile (128x16) -> As transposed
#pragma unroll
        for (int i = 0; i < 2; i++) {
            int id  = i * 256 + t;
            int row = id >> 2;          // 0..127
            int c4  = (id & 3) << 2;    // 0,4,8,12
            const float4 v = *(const float4*)(A + (size_t)(m0 + row) * 256 + k0 + c4);
            As[c4 + 0][row] = v.x;
            As[c4 + 1][row] = v.y;
            As[c4 + 2][row] = v.z;
            As[c4 + 3][row] = v.w;
        }
        // Load B tile (16x64)
        {
            int row = t >> 4;           // 0..15
            int c4  = (t & 15) << 2;    // 0..60
            *(float4*)(&Bs[row][c4]) = *(const float4*)(B + (size_t)(k0 + row) * 256 + n0 + c4);
        }
        __syncthreads();
#pragma unroll
        for (int k = 0; k < GBK; k++) {
            float a[8], bb[4];
#pragma unroll
            for (int i = 0; i < 8; i++) a[i] = As[k][tm0 + i];
#pragma unroll
            for (int j = 0; j < 4; j++) bb[j] = Bs[k][tn0 + j];
#pragma unroll
            for (int i = 0; i < 8; i++)
#pragma unroll
                for (int j = 0; j < 4; j++) acc[i][j] = fmaf(a[i], bb[j], acc[i][j]);
        }
        __syncthreads();
    }

#pragma unroll
    for (int i = 0; i < 8; i++) {
        int m = m0 + tm0 + i;
        float4 v = make_float4(acc[i][0], acc[i][1], acc[i][2], acc[i][3]);
        if (addpos) {
            int y  = (m >> 6) & 63;
            int x  = m & 63;
            int qy = y - min(max(y, 3), 60) + 3;
            int qx = x - min(max(x, 3), 60) + 3;
            const float4 pe = *(const float4*)(pos + (size_t)(qy * 7 + qx) * 256 + n0 + tn0);
            v.x += pe.x; v.y += pe.y; v.z += pe.z; v.w += pe.w;
        }
        *(float4*)(C + (size_t)m * 256 + n0 + tn0) = v;
    }
}

__global__ __launch_bounds__(256) void qkv_kernel(const float* __restrict__ X,
                                                  const float* __restrict__ Wq,
                                                  const float* __restrict__ Wk,
                                                  const float* __restrict__ Wv,
                                                  const float* __restrict__ pos)
{
    int mat = blockIdx.z;
    const float* W = (mat == 0) ? Wq : ((mat == 1) ? Wk : Wv);
    float* O       = (mat == 0) ? g_Q : ((mat == 1) ? g_K : g_V);
    sgemm_256(X, W, O, pos, mat == 0);
}

__global__ __launch_bounds__(256) void out_kernel(const float* __restrict__ Wo,
                                                  float* __restrict__ out)
{
    sgemm_256(g_att, Wo, out, nullptr, false);
}

// ---------------------------------------------------------------------------
// Attention v3: two-phase, single K/V smem buffer -> 46KB smem, 4 blocks/SM.
// Phase 1: K halo + P resident; compute 49 scores into registers.
// Phase 2: reload V halo into the SAME buffer (L2-hot); exp+accumulate.
// Thread = (pixel, head). Block = 16x8 pixel tile, 1 head, 128 threads.
// ---------------------------------------------------------------------------
#define TW 16
#define TH 8
#define HW 22
#define NR (HW*14)   // 308

__global__ __launch_bounds__(128, 4) void attn_kernel(const float* __restrict__ pos)
{
    extern __shared__ float4 sm4[];
    float4* KV  = sm4;              // [8][NR]  (K in phase 1, V in phase 2)
    float4* Ps4 = sm4 + 8 * NR;     // [8][49]

    const int bx = blockIdx.x;      // 0..31
    const int h  = blockIdx.y;
    const int b  = blockIdx.z;
    const int Ty = (bx >> 2) * TH;
    const int Tx = (bx & 3) * TW;
    const int t  = threadIdx.x;
    const int hb = h * 32;

    // ---- Phase 0: load K halo + P ----
    for (int i = t; i < NR * 8; i += 128) {
        int r  = i >> 3;
        int f4 = i & 7;
        int ry = r / HW;
        int rx = r - ry * HW;
        int gy = min(max(Ty - 3 + ry, 0), 63);
        int gx = min(max(Tx - 3 + rx, 0), 63);
        size_t off = ((size_t)(((b << 6) + gy) << 6) + gx) * 256 + hb + (f4 << 2);
        KV[f4 * NR + r] = *(const float4*)(g_K + off);
    }
    for (int i = t; i < 49 * 8; i += 128) {
        int s  = i >> 3;
        int f4 = i & 7;
        Ps4[f4 * 49 + s] = *(const float4*)(pos + (size_t)s * 256 + hb + (f4 << 2));
    }
    __syncthreads();

    const int py = t >> 4, px = t & 15;
    const int gy = Ty + py, gx = Tx + px;
    const int pr0 = min(max(gy, 3), 60) - Ty;
    const int pc0 = min(max(gx, 3), 60) - Tx;
    const size_t gp = ((size_t)(((b << 6) + gy) << 6) + gx) * 256 + hb;

    const float scale = 0.17677669529663687f;  // 1/sqrt(32)
    float4 q[8];
#pragma unroll
    for (int f4 = 0; f4 < 8; f4++) {
        float4 v = *(const float4*)(g_Q + gp + (f4 << 2));
        v.x *= scale; v.y *= scale; v.z *= scale; v.w *= scale;
        q[f4] = v;
    }

    // ---- Phase 1: scores ----
    float sc[49];
#pragma unroll
    for (int dy = 0; dy < 7; dy++) {
        const int r0 = (pr0 + dy) * HW + pc0;
        const int s0 = dy * 7;
#pragma unroll
        for (int dx = 0; dx < 7; dx++) {
            const int r = r0 + dx;
            const int s = s0 + dx;
            float4 d = make_float4(0.f, 0.f, 0.f, 0.f);
#pragma unroll
            for (int f4 = 0; f4 < 8; f4++) {
                const float4 k = KV[f4 * NR + r];
                const float4 p = Ps4[f4 * 49 + s];
                d.x = fmaf(q[f4].x, k.x + p.x, d.x);
                d.y = fmaf(q[f4].y, k.y + p.y, d.y);
                d.z = fmaf(q[f4].z, k.z + p.z, d.z);
                d.w = fmaf(q[f4].w, k.w + p.w, d.w);
            }
            sc[s] = (d.x + d.y) + (d.z + d.w);
        }
    }
    __syncthreads();   // everyone done reading K

    // ---- Phase 1.5: reload buffer with V halo (L2-hot) ----
    for (int i = t; i < NR * 8; i += 128) {
        int r  = i >> 3;
        int f4 = i & 7;
        int ry = r / HW;
        int rx = r - ry * HW;
        int gyv = min(max(Ty - 3 + ry, 0), 63);
        int gxv = min(max(Tx - 3 + rx, 0), 63);
        size_t off = ((size_t)(((b << 6) + gyv) << 6) + gxv) * 256 + hb + (f4 << 2);
        KV[f4 * NR + r] = *(const float4*)(g_V + off);
    }
    __syncthreads();

    // ---- Phase 2: exp + weighted V accumulate ----
    float l = 0.f;
    float4 acc[8];
#pragma unroll
    for (int f4 = 0; f4 < 8; f4++) acc[f4] = make_float4(0.f, 0.f, 0.f, 0.f);

#pragma unroll
    for (int dy = 0; dy < 7; dy++) {
        const int r0 = (pr0 + dy) * HW + pc0;
        const int s0 = dy * 7;
#pragma unroll
        for (int dx = 0; dx < 7; dx++) {
            const int r = r0 + dx;
            const float w = __expf(sc[s0 + dx]);
            l += w;
#pragma unroll
            for (int f4 = 0; f4 < 8; f4++) {
                const float4 v = KV[f4 * NR + r];
                acc[f4].x = fmaf(w, v.x, acc[f4].x);
                acc[f4].y = fmaf(w, v.y, acc[f4].y);
                acc[f4].z = fmaf(w, v.z, acc[f4].z);
                acc[f4].w = fmaf(w, v.w, acc[f4].w);
            }
        }
    }

    const float inv = __fdividef(1.f, l + 1e-8f);
#pragma unroll
    for (int f4 = 0; f4 < 8; f4++) {
        float4 o = acc[f4];
        o.x *= inv; o.y *= inv; o.z *= inv; o.w *= inv;
        *(float4*)(g_att + gp + (f4 << 2)) = o;
    }
}

// ---------------------------------------------------------------------------
extern "C" void kernel_launch(void* const* d_in, const int* in_sizes, int n_in,
                              void* d_out, int out_size)
{
    const float* x   = (const float*)d_in[0];
    const float* Wq  = (const float*)d_in[1];
    const float* Wk  = (const float*)d_in[2];
    const float* Wv  = (const float*)d_in[3];
    const float* Wo  = (const float*)d_in[4];
    const float* pos = (const float*)d_in[5];

    // 1) QKV projections (+pos epilogue on Q)
    qkv_kernel<<<dim3(Cd / GBN, NPIX / GBM, 3), 256>>>(x, Wq, Wk, Wv, pos);

    // 2) Local attention (two-phase, 46KB smem -> 4 blocks/SM)
    const int smem = (8 * NR + 8 * 49) * (int)sizeof(float4); // 45,696 B
    cudaFuncSetAttribute(attn_kernel, cudaFuncAttributeMaxDynamicSharedMemorySize, smem);
    attn_kernel<<<dim3(32, Hd, Bd), 128, smem>>>(pos);

    // 3) Output projection
    out_kernel<<<dim3(Cd / GBN, NPIX / GBM, 1), 256>>>(Wo, (float*)d_out);
}

// round 9
// speedup vs baseline: 1.2575x; 1.0355x over previous
#include <cuda_runtime.h>
#include <cuda_bf16.h>
#include <cstdint>

// Problem constants
#define Bd 4
#define Cd 256
#define Hd 8
#define NPIX 16384

// f32 intermediates
__device__ float g_Q[NPIX*Cd];
__device__ float g_K[NPIX*Cd];
__device__ float g_V[NPIX*Cd];

// split-bf16 operands
__device__ unsigned short g_Xhi[NPIX*Cd];
__device__ unsigned short g_Xlo[NPIX*Cd];
__device__ unsigned short g_AThi[NPIX*Cd];     // attention output hi
__device__ unsigned short g_ATlo[NPIX*Cd];     // attention output lo
__device__ unsigned short g_Wthi[4*Cd*Cd];     // W^T  [mat][n][k]
__device__ unsigned short g_Wtlo[4*Cd*Cd];

// ---------------------------------------------------------------------------
// Prep: split fp32 -> (hi, lo) bf16
// ---------------------------------------------------------------------------
__device__ __forceinline__ void split1(float f, unsigned short& h, unsigned short& l) {
    __nv_bfloat16 hb = __float2bfloat16_rn(f);
    __nv_bfloat16 lb = __float2bfloat16_rn(f - __bfloat162float(hb));
    h = __bfloat16_as_ushort(hb);
    l = __bfloat16_as_ushort(lb);
}

__global__ void prep_x_kernel(const float* __restrict__ X)
{
    int g = blockIdx.x * blockDim.x + threadIdx.x;   // NPIX*64
    int e = g << 2;
    const float4 v = *(const float4*)(X + e);
    ushort4 h, l;
    split1(v.x, h.x, l.x); split1(v.y, h.y, l.y);
    split1(v.z, h.z, l.z); split1(v.w, h.w, l.w);
    *(ushort4*)(g_Xhi + e) = h;
    *(ushort4*)(g_Xlo + e) = l;
}

__global__ void prep_w_kernel(const float* __restrict__ Wq,
                              const float* __restrict__ Wk,
                              const float* __restrict__ Wv,
                              const float* __restrict__ Wo)
{
    int g = blockIdx.x * blockDim.x + threadIdx.x;   // 4*256*64
    int mat = g >> 14;
    int rem = g & 16383;
    int n   = rem >> 6;
    int k0  = (rem & 63) << 2;
    const float* W = (mat == 0) ? Wq : (mat == 1) ? Wk : (mat == 2) ? Wv : Wo;
    ushort4 h, l;
    split1(W[(size_t)(k0 + 0) * 256 + n], h.x, l.x);
    split1(W[(size_t)(k0 + 1) * 256 + n], h.y, l.y);
    split1(W[(size_t)(k0 + 2) * 256 + n], h.z, l.z);
    split1(W[(size_t)(k0 + 3) * 256 + n], h.w, l.w);
    int base = (((mat << 8) | n) << 8) + k0;
    *(ushort4*)(g_Wthi + base) = h;
    *(ushort4*)(g_Wtlo + base) = l;
}

// ---------------------------------------------------------------------------
// bf16 mma.sync GEMM:  C[16384 x 256] = A x W, via K'=768 split trick
//   iters 0-15 : Ahi * Bhi   iters 16-31: Ahi * Blo   iters 32-47: Alo * Bhi
// CTA 128x64, 256 threads (8 warps, 4m x 2n), warp tile 32x32 (2 x 4 frags).
// ---------------------------------------------------------------------------
#define BM 128
#define BN 64
#define SSTR 24   // bf16 elems per smem row (48B = 12 words): conflict-free frags

__device__ __forceinline__ void mma16816(float c[4], const unsigned a[4], const unsigned b[2]) {
    asm volatile(
        "mma.sync.aligned.m16n8k16.row.col.f32.bf16.bf16.f32 "
        "{%0,%1,%2,%3}, {%4,%5,%6,%7}, {%8,%9}, {%0,%1,%2,%3};"
        : "+f"(c[0]), "+f"(c[1]), "+f"(c[2]), "+f"(c[3])
        : "r"(a[0]), "r"(a[1]), "r"(a[2]), "r"(a[3]), "r"(b[0]), "r"(b[1]));
}

__device__ __forceinline__ void mma_gemm(const unsigned short* __restrict__ Ahi,
                                         const unsigned short* __restrict__ Alo,
                                         const unsigned short* __restrict__ Bhi,
                                         const unsigned short* __restrict__ Blo,
                                         float* __restrict__ C,
                                         const float* __restrict__ pos,
                                         bool addpos)
{
    __shared__ unsigned short As[2][BM * SSTR];
    __shared__ unsigned short Bs[2][BN * SSTR];

    const int t    = threadIdx.x;
    const int m0   = blockIdx.y * BM;
    const int n0   = blockIdx.x * BN;
    const int wid  = t >> 5;
    const int lane = t & 31;
    const int grp  = lane >> 2;        // 0..7
    const int tig  = lane & 3;         // 0..3
    const int wm0  = (wid >> 1) << 5;  // 0,32,64,96
    const int wn0  = (wid & 1) << 5;   // 0,32

    const int arow = t >> 1;           // 0..127
    const int aseg = (t & 1) << 3;     // 0 / 8
    const int brow = (t & 127) >> 1;   // 0..63 (only t<128 stores B)

    uint4 ra, rb;
    auto ldg = [&](int iter) {
        const int ph = iter >> 4;
        const int kk = (iter & 15) << 4;
        const unsigned short* Asrc = (ph < 2) ? Ahi : Alo;
        const unsigned short* Bsrc = (ph == 1) ? Blo : Bhi;
        ra = *(const uint4*)(Asrc + (size_t)(m0 + arow) * 256 + kk + aseg);
        if (t < 128)
            rb = *(const uint4*)(Bsrc + (size_t)(n0 + brow) * 256 + kk + aseg);
    };
    auto sts = [&](int buf) {
        *(uint4*)(&As[buf][arow * SSTR + aseg]) = ra;
        if (t < 128)
            *(uint4*)(&Bs[buf][brow * SSTR + aseg]) = rb;
    };

    float acc[2][4][4];
#pragma unroll
    for (int mi = 0; mi < 2; mi++)
#pragma unroll
        for (int ni = 0; ni < 4; ni++)
#pragma unroll
            for (int j = 0; j < 4; j++) acc[mi][ni][j] = 0.f;

    ldg(0); sts(0); __syncthreads();

    for (int iter = 0; iter < 48; iter++) {
        const int buf = iter & 1;
        const bool more = (iter < 47);
        if (more) ldg(iter + 1);

        const unsigned* As32 = (const unsigned*)&As[buf][0];
        const unsigned* Bs32 = (const unsigned*)&Bs[buf][0];
        unsigned au[2][4], bu[4][2];
#pragma unroll
        for (int mi = 0; mi < 2; mi++) {
            const int r0 = wm0 + mi * 16 + grp;
            au[mi][0] = As32[r0 * 12 + tig];
            au[mi][1] = As32[(r0 + 8) * 12 + tig];
            au[mi][2] = As32[r0 * 12 + tig + 4];
            au[mi][3] = As32[(r0 + 8) * 12 + tig + 4];
        }
#pragma unroll
        for (int ni = 0; ni < 4; ni++) {
            const int c0 = wn0 + ni * 8 + grp;
            bu[ni][0] = Bs32[c0 * 12 + tig];
            bu[ni][1] = Bs32[c0 * 12 + tig + 4];
        }
#pragma unroll
        for (int mi = 0; mi < 2; mi++)
#pragma unroll
            for (int ni = 0; ni < 4; ni++)
                mma16816(acc[mi][ni], au[mi], bu[ni]);

        if (more) { sts(buf ^ 1); __syncthreads(); }
    }

    // Epilogue
#pragma unroll
    for (int mi = 0; mi < 2; mi++) {
#pragma unroll
        for (int half = 0; half < 2; half++) {
            const int m = m0 + wm0 + mi * 16 + grp + half * 8;
            const float* pe = nullptr;
            if (addpos) {
                int y  = (m >> 6) & 63;
                int x  = m & 63;
                int qy = y - min(max(y, 3), 60) + 3;
                int qx = x - min(max(x, 3), 60) + 3;
                pe = pos + (size_t)(qy * 7 + qx) * 256;
            }
#pragma unroll
            for (int ni = 0; ni < 4; ni++) {
                const int n = n0 + wn0 + ni * 8 + tig * 2;
                float2 v = make_float2(acc[mi][ni][half * 2], acc[mi][ni][half * 2 + 1]);
                if (addpos) {
                    const float2 p = *(const float2*)(pe + n);
                    v.x += p.x; v.y += p.y;
                }
                *(float2*)(C + (size_t)m * 256 + n) = v;
            }
        }
    }
}

__global__ __launch_bounds__(256) void qkv_kernel(const float* __restrict__ pos)
{
    const int mat = blockIdx.z;
    float* C = (mat == 0) ? g_Q : (mat == 1) ? g_K : g_V;
    mma_gemm(g_Xhi, g_Xlo,
             g_Wthi + (size_t)mat * 65536, g_Wtlo + (size_t)mat * 65536,
             C, pos, mat == 0);
}

__global__ __launch_bounds__(256) void out_kernel(float* __restrict__ out)
{
    mma_gemm(g_AThi, g_ATlo,
             g_Wthi + (size_t)3 * 65536, g_Wtlo + (size_t)3 * 65536,
             out, nullptr, false);
}

// ---------------------------------------------------------------------------
// Attention (R8-proven two-phase): epilogue now emits hi/lo bf16 directly.
// ---------------------------------------------------------------------------
#define TW 16
#define TH 8
#define HW 22
#define NR (HW*14)   // 308

__global__ __launch_bounds__(128, 4) void attn_kernel(const float* __restrict__ pos)
{
    extern __shared__ float4 sm4[];
    float4* KV  = sm4;              // [8][NR]  (K then V)
    float4* Ps4 = sm4 + 8 * NR;     // [8][49]

    const int bx = blockIdx.x;
    const int h  = blockIdx.y;
    const int b  = blockIdx.z;
    const int Ty = (bx >> 2) * TH;
    const int Tx = (bx & 3) * TW;
    const int t  = threadIdx.x;
    const int hb = h * 32;

    for (int i = t; i < NR * 8; i += 128) {
        int r  = i >> 3;
        int f4 = i & 7;
        int ry = r / HW;
        int rx = r - ry * HW;
        int gy = min(max(Ty - 3 + ry, 0), 63);
        int gx = min(max(Tx - 3 + rx, 0), 63);
        size_t off = ((size_t)(((b << 6) + gy) << 6) + gx) * 256 + hb + (f4 << 2);
        KV[f4 * NR + r] = *(const float4*)(g_K + off);
    }
    for (int i = t; i < 49 * 8; i += 128) {
        int s  = i >> 3;
        int f4 = i & 7;
        Ps4[f4 * 49 + s] = *(const float4*)(pos + (size_t)s * 256 + hb + (f4 << 2));
    }
    __syncthreads();

    const int py = t >> 4, px = t & 15;
    const int gy = Ty + py, gx = Tx + px;
    const int pr0 = min(max(gy, 3), 60) - Ty;
    const int pc0 = min(max(gx, 3), 60) - Tx;
    const size_t gp = ((size_t)(((b << 6) + gy) << 6) + gx) * 256 + hb;

    const float scale = 0.17677669529663687f;  // 1/sqrt(32)
    float4 q[8];
#pragma unroll
    for (int f4 = 0; f4 < 8; f4++) {
        float4 v = *(const float4*)(g_Q + gp + (f4 << 2));
        v.x *= scale; v.y *= scale; v.z *= scale; v.w *= scale;
        q[f4] = v;
    }

    float sc[49];
#pragma unroll
    for (int dy = 0; dy < 7; dy++) {
        const int r0 = (pr0 + dy) * HW + pc0;
        const int s0 = dy * 7;
#pragma unroll
        for (int dx = 0; dx < 7; dx++) {
            const int r = r0 + dx;
            const int s = s0 + dx;
            float4 d = make_float4(0.f, 0.f, 0.f, 0.f);
#pragma unroll
            for (int f4 = 0; f4 < 8; f4++) {
                const float4 k = KV[f4 * NR + r];
                const float4 p = Ps4[f4 * 49 + s];
                d.x = fmaf(q[f4].x, k.x + p.x, d.x);
                d.y = fmaf(q[f4].y, k.y + p.y, d.y);
                d.z = fmaf(q[f4].z, k.z + p.z, d.z);
                d.w = fmaf(q[f4].w, k.w + p.w, d.w);
            }
            sc[s] = (d.x + d.y) + (d.z + d.w);
        }
    }
    __syncthreads();

    for (int i = t; i < NR * 8; i += 128) {
        int r  = i >> 3;
        int f4 = i & 7;
        int ry = r / HW;
        int rx = r - ry * HW;
        int gyv = min(max(Ty - 3 + ry, 0), 63);
        int gxv = min(max(Tx - 3 + rx, 0), 63);
        size_t off = ((size_t)(((b << 6) + gyv) << 6) + gxv) * 256 + hb + (f4 << 2);
        KV[f4 * NR + r] = *(const float4*)(g_V + off);
    }
    __syncthreads();

    float l = 0.f;
    float4 acc[8];
#pragma unroll
    for (int f4 = 0; f4 < 8; f4++) acc[f4] = make_float4(0.f, 0.f, 0.f, 0.f);

#pragma unroll
    for (int dy = 0; dy < 7; dy++) {
        const int r0 = (pr0 + dy) * HW + pc0;
        const int s0 = dy * 7;
#pragma unroll
        for (int dx = 0; dx < 7; dx++) {
            const int r = r0 + dx;
            const float w = __expf(sc[s0 + dx]);
            l += w;
#pragma unroll
            for (int f4 = 0; f4 < 8; f4++) {
                const float4 v = KV[f4 * NR + r];
                acc[f4].x = fmaf(w, v.x, acc[f4].x);
                acc[f4].y = fmaf(w, v.y, acc[f4].y);
                acc[f4].z = fmaf(w, v.z, acc[f4].z);
                acc[f4].w = fmaf(w, v.w, acc[f4].w);
            }
        }
    }

    const float inv = __fdividef(1.f, l + 1e-8f);
#pragma unroll
    for (int f4 = 0; f4 < 8; f4++) {
        float o[4] = {acc[f4].x * inv, acc[f4].y * inv, acc[f4].z * inv, acc[f4].w * inv};
        ushort4 hv, lv;
        split1(o[0], hv.x, lv.x); split1(o[1], hv.y, lv.y);
        split1(o[2], hv.z, lv.z); split1(o[3], hv.w, lv.w);
        *(ushort4*)(g_AThi + gp + (f4 << 2)) = hv;
        *(ushort4*)(g_ATlo + gp + (f4 << 2)) = lv;
    }
}

// ---------------------------------------------------------------------------
extern "C" void kernel_launch(void* const* d_in, const int* in_sizes, int n_in,
                              void* d_out, int out_size)
{
    const float* x   = (const float*)d_in[0];
    const float* Wq  = (const float*)d_in[1];
    const float* Wk  = (const float*)d_in[2];
    const float* Wv  = (const float*)d_in[3];
    const float* Wo  = (const float*)d_in[4];
    const float* pos = (const float*)d_in[5];

    // 0) split-bf16 prep
    prep_w_kernel<<<256, 256>>>(Wq, Wk, Wv, Wo);
    prep_x_kernel<<<4096, 256>>>(x);

    // 1) QKV projections via HMMA (+pos epilogue on Q)
    qkv_kernel<<<dim3(Cd / BN, NPIX / BM, 3), 256>>>(pos);

    // 2) Local attention (emits split-bf16 output)
    const int smem = (8 * NR + 8 * 49) * (int)sizeof(float4); // 45,696 B
    cudaFuncSetAttribute(attn_kernel, cudaFuncAttributeMaxDynamicSharedMemorySize, smem);
    attn_kernel<<<dim3(32, Hd, Bd), 128, smem>>>(pos);

    // 3) Output projection via HMMA
    out_kernel<<<dim3(Cd / BN, NPIX / BM, 1), 256>>>((float*)d_out);
}